// round 2
// baseline (speedup 1.0000x reference)
#include <cuda_runtime.h>

#define BH_  16
#define SEQ  2048
#define HD   64
#define OUT_ELEMS (BH_*SEQ*HD)   // 2097152 floats; p_attn region follows

__device__ float g_rowsum[BH_ * SEQ];   // 32768 floats of scratch (static: allowed)

__global__ void zero_rs() {
    int i = blockIdx.x * 256 + threadIdx.x;
    if (i < BH_ * SEQ) g_rowsum[i] = 0.0f;
}

// ---------------------------------------------------------------------------
// Kernel A: S = Q K^T (128x128 tile), fused e = mask ? (p+1e-12)*exp(s/8) : 0
// writes unnormalized e into p_attn region, accumulates row sums.
// ---------------------------------------------------------------------------
__global__ __launch_bounds__(256, 2) void scores_k(
    const float* __restrict__ Q, const float* __restrict__ K,
    const int*  __restrict__ M, const float* __restrict__ P,
    float* __restrict__ E)
{
    __shared__ float Qs[8][128];
    __shared__ float Ks[8][128];
    const int bh = blockIdx.z;
    const int q0 = blockIdx.y * 128;
    const int k0 = blockIdx.x * 128;
    const int t  = threadIdx.x;
    const int tx = t & 15, ty = t >> 4;

    float acc[8][8];
#pragma unroll
    for (int i = 0; i < 8; i++)
#pragma unroll
        for (int j = 0; j < 8; j++) acc[i][j] = 0.0f;

    const float* Qb = Q + ((size_t)bh * SEQ + q0) * HD;
    const float* Kb = K + ((size_t)bh * SEQ + k0) * HD;
    const int lr = t >> 1;          // 0..127
    const int ld = (t & 1) * 4;     // 0 or 4 within 8-wide d-chunk

    for (int dc = 0; dc < 8; ++dc) {
        float4 qv = *(const float4*)(Qb + (size_t)lr * HD + dc * 8 + ld);
        float4 kv = *(const float4*)(Kb + (size_t)lr * HD + dc * 8 + ld);
        Qs[ld + 0][lr] = qv.x; Qs[ld + 1][lr] = qv.y;
        Qs[ld + 2][lr] = qv.z; Qs[ld + 3][lr] = qv.w;
        Ks[ld + 0][lr] = kv.x; Ks[ld + 1][lr] = kv.y;
        Ks[ld + 2][lr] = kv.z; Ks[ld + 3][lr] = kv.w;
        __syncthreads();
#pragma unroll
        for (int dd = 0; dd < 8; ++dd) {
            float a[8], b[8];
            float4 a0 = *(const float4*)&Qs[dd][ty * 4];
            float4 a1 = *(const float4*)&Qs[dd][64 + ty * 4];
            float4 b0 = *(const float4*)&Ks[dd][tx * 4];
            float4 b1 = *(const float4*)&Ks[dd][64 + tx * 4];
            a[0] = a0.x; a[1] = a0.y; a[2] = a0.z; a[3] = a0.w;
            a[4] = a1.x; a[5] = a1.y; a[6] = a1.z; a[7] = a1.w;
            b[0] = b0.x; b[1] = b0.y; b[2] = b0.z; b[3] = b0.w;
            b[4] = b1.x; b[5] = b1.y; b[6] = b1.z; b[7] = b1.w;
#pragma unroll
            for (int i = 0; i < 8; i++)
#pragma unroll
                for (int j = 0; j < 8; j++)
                    acc[i][j] += a[i] * b[j];
        }
        __syncthreads();
    }

    // Epilogue: e = mask ? (p+1e-12) * exp(s * 0.125) : 0 ; row sums
    const size_t mbase = ((size_t)bh * SEQ) * SEQ;
#pragma unroll
    for (int i = 0; i < 8; i++) {
        const int r = q0 + ty * 4 + (i & 3) + ((i >> 2) << 6);
        const size_t rowb = mbase + (size_t)r * SEQ + k0;
        float rs = 0.0f;
#pragma unroll
        for (int g = 0; g < 2; ++g) {
            const int c = tx * 4 + g * 64;
            int4   m4 = *(const int4*)  (M + rowb + c);
            float4 p4 = *(const float4*)(P + rowb + c);
            float4 e;
            e.x = m4.x ? (p4.x + 1e-12f) * __expf(acc[i][g * 4 + 0] * 0.125f) : 0.0f;
            e.y = m4.y ? (p4.y + 1e-12f) * __expf(acc[i][g * 4 + 1] * 0.125f) : 0.0f;
            e.z = m4.z ? (p4.z + 1e-12f) * __expf(acc[i][g * 4 + 2] * 0.125f) : 0.0f;
            e.w = m4.w ? (p4.w + 1e-12f) * __expf(acc[i][g * 4 + 3] * 0.125f) : 0.0f;
            *(float4*)(E + rowb + c) = e;
            rs += (e.x + e.y) + (e.z + e.w);
        }
        // reduce across the 16 tx-threads (they are a contiguous 16-lane group)
#pragma unroll
        for (int off = 8; off > 0; off >>= 1)
            rs += __shfl_down_sync(0xffffffffu, rs, off, 16);
        if (tx == 0) atomicAdd(&g_rowsum[bh * SEQ + r], rs);
    }
}

// ---------------------------------------------------------------------------
// Kernel B: out = (E * V) / rowsum   (256 q-rows x 64 d per CTA)
// ---------------------------------------------------------------------------
__global__ __launch_bounds__(256, 2) void pv_k(
    const float* __restrict__ E, const float* __restrict__ V,
    float* __restrict__ O)
{
    __shared__ float Es[8][256];
    __shared__ float Vs[8][64];
    const int bh = blockIdx.y;
    const int q0 = blockIdx.x * 256;
    const int t  = threadIdx.x;
    const int tx = t & 7, ty = t >> 3;   // tx: d-groups, ty: q-groups (0..31)

    float acc[8][8];
#pragma unroll
    for (int i = 0; i < 8; i++)
#pragma unroll
        for (int j = 0; j < 8; j++) acc[i][j] = 0.0f;

    const float* Eb = E + ((size_t)bh * SEQ + q0) * SEQ;
    const float* Vb = V + (size_t)bh * SEQ * HD;

    for (int kc = 0; kc < SEQ / 8; ++kc) {
        float4 e0 = *(const float4*)(Eb + (size_t)t * SEQ + kc * 8);
        float4 e1 = *(const float4*)(Eb + (size_t)t * SEQ + kc * 8 + 4);
        Es[0][t] = e0.x; Es[1][t] = e0.y; Es[2][t] = e0.z; Es[3][t] = e0.w;
        Es[4][t] = e1.x; Es[5][t] = e1.y; Es[6][t] = e1.z; Es[7][t] = e1.w;
        if (t < 128) {
            const int kk = t >> 4, d4 = (t & 15) * 4;
            float4 v = *(const float4*)(Vb + (size_t)(kc * 8 + kk) * HD + d4);
            *(float4*)&Vs[kk][d4] = v;
        }
        __syncthreads();
#pragma unroll
        for (int kk = 0; kk < 8; ++kk) {
            float a[8], b[8];
            float4 a0 = *(const float4*)&Es[kk][ty * 4];
            float4 a1 = *(const float4*)&Es[kk][128 + ty * 4];
            float4 b0 = *(const float4*)&Vs[kk][tx * 4];
            float4 b1 = *(const float4*)&Vs[kk][32 + tx * 4];
            a[0] = a0.x; a[1] = a0.y; a[2] = a0.z; a[3] = a0.w;
            a[4] = a1.x; a[5] = a1.y; a[6] = a1.z; a[7] = a1.w;
            b[0] = b0.x; b[1] = b0.y; b[2] = b0.z; b[3] = b0.w;
            b[4] = b1.x; b[5] = b1.y; b[6] = b1.z; b[7] = b1.w;
#pragma unroll
            for (int i = 0; i < 8; i++)
#pragma unroll
                for (int j = 0; j < 8; j++)
                    acc[i][j] += a[i] * b[j];
        }
        __syncthreads();
    }

#pragma unroll
    for (int i = 0; i < 8; i++) {
        const int r = q0 + ty * 4 + (i & 3) + ((i >> 2) << 7);
        const float inv = 1.0f / g_rowsum[bh * SEQ + r];
        const size_t ob = ((size_t)bh * SEQ + r) * HD;
#pragma unroll
        for (int g = 0; g < 2; ++g) {
            float4 o;
            o.x = acc[i][g * 4 + 0] * inv;
            o.y = acc[i][g * 4 + 1] * inv;
            o.z = acc[i][g * 4 + 2] * inv;
            o.w = acc[i][g * 4 + 3] * inv;
            *(float4*)(O + ob + tx * 4 + g * 32) = o;
        }
    }
}

// ---------------------------------------------------------------------------
// Kernel C: in-place normalize p_attn = E / rowsum
// ---------------------------------------------------------------------------
__global__ __launch_bounds__(256) void norm_k(float* __restrict__ E)
{
    const int row = blockIdx.x;             // 0..32767
    const float inv = 1.0f / g_rowsum[row];
    float4* p = (float4*)(E + (size_t)row * SEQ);
    const int i = threadIdx.x;
    float4 v0 = p[i];
    v0.x *= inv; v0.y *= inv; v0.z *= inv; v0.w *= inv;
    p[i] = v0;
    float4 v1 = p[i + 256];
    v1.x *= inv; v1.y *= inv; v1.z *= inv; v1.w *= inv;
    p[i + 256] = v1;
}

extern "C" void kernel_launch(void* const* d_in, const int* in_sizes, int n_in,
                              void* d_out, int out_size) {
    const float* Q = (const float*)d_in[0];
    const float* K = (const float*)d_in[1];
    const float* V = (const float*)d_in[2];
    const int*   M = (const int*)  d_in[3];
    const float* P = (const float*)d_in[4];
    float* out = (float*)d_out;
    float* E   = out + OUT_ELEMS;           // p_attn region

    zero_rs<<<(BH_ * SEQ + 255) / 256, 256>>>();
    scores_k<<<dim3(16, 16, BH_), 256>>>(Q, K, M, P, E);
    pv_k<<<dim3(SEQ / 256, BH_), 256>>>(E, V, out);
    norm_k<<<BH_ * SEQ, 256>>>(E);
}